// round 9
// baseline (speedup 1.0000x reference)
#include <cuda_runtime.h>
#include <cuda_fp16.h>
#include <cstdint>

#define B_ 64
#define S_ 2048
#define D_ 512

#define TM 64            // M rows per CTA
#define TK 32            // K per stage tile
#define NKT (D_ / TK)    // 16 k-tiles
#define NSCH 8           // context S-chunks

// ---------------- scratch globals ----------------
__device__ float g_wq[B_ * D_];
__device__ float g_scores[B_ * S_];
__device__ float g_stats[2 * B_];
__device__ float g_ctx[NSCH][B_ * D_];
// Wc as fp16 in m16n8k16-fragment order
__device__ __align__(16) uint4 g_wcH[NKT * 2048];
// fp16 copy of memory_bank, written by scores_kernel as a side effect (134 MB)
__device__ __align__(16) __half g_mbH[(size_t)B_ * S_ * D_];

// ---------------- helpers ----------------
__device__ __forceinline__ float fast_tanh(float x) {
    float xc = fminf(fmaxf(x, -15.f), 15.f);
    float e = __expf(2.f * xc);
    return __fdividef(e - 1.f, e + 1.f);
}
// memory_lengths dtype sniff (int64 vs int32): word[1]==0 iff int64 (LE)
__device__ __forceinline__ int load_len(const void* lens, int b) {
    const int* p32 = (const int*)lens;
    if (p32[1] == 0) return (int)((const long long*)lens)[b];
    return p32[b];
}
__device__ __forceinline__ uint32_t smem_u32(const void* p) {
    uint32_t a;
    asm("{ .reg .u64 t; cvta.to.shared.u64 t, %1; cvt.u32.u64 %0, t; }" : "=r"(a) : "l"(p));
    return a;
}
__device__ __forceinline__ void cp_async16(uint32_t dst, const void* src) {
    asm volatile("cp.async.cg.shared.global [%0], [%1], 16;" :: "r"(dst), "l"(src));
}
__device__ __forceinline__ uint32_t packh2(float a, float b) {
    __half2 h = __floats2half2_rn(a, b);
    return *(uint32_t*)&h;
}
__device__ __forceinline__ void mma_fp16(float* c, const uint32_t* a,
                                         uint32_t b0, uint32_t b1) {
    asm volatile(
        "mma.sync.aligned.m16n8k16.row.col.f32.f16.f16.f32 "
        "{%0,%1,%2,%3}, {%4,%5,%6,%7}, {%8,%9}, {%0,%1,%2,%3};"
        : "+f"(c[0]), "+f"(c[1]), "+f"(c[2]), "+f"(c[3])
        : "r"(a[0]), "r"(a[1]), "r"(a[2]), "r"(a[3]), "r"(b0), "r"(b1));
}

// ============================================================
// Kernel 0: fused prep (Wc -> fp16 fragment order) + wq GEMV.
// grid 128, block 512. bid<64: prep; bid>=64: wq for batch bid-64.
// ============================================================
__global__ void prep_kernel(const float* __restrict__ Wc,
                            const float* __restrict__ src,
                            const float* __restrict__ Wq,
                            const float* __restrict__ bq) {
    int bid = blockIdx.x, tid = threadIdx.x;
    if (bid < 64) {
        int p = bid * 512 + tid;     // 32768 uint4
        int lane = p & 31;
        int j2   = (p >> 5) & 3;
        int wc   = (p >> 7) & 7;
        int kk   = (p >> 10) & 1;
        int kb   = (p >> 11) & 15;
        int g = lane >> 2, t = lane & 3;
        int ne = wc * 64 + j2 * 16 + g;
        int no = ne + 8;
        int k0 = kb * 32 + kk * 16 + 2 * t;
        const float* we = Wc + (size_t)ne * D_;
        const float* wo = Wc + (size_t)no * D_;
        uint4 f;
        f.x = packh2(we[k0],     we[k0 + 1]);
        f.y = packh2(we[k0 + 8], we[k0 + 9]);
        f.z = packh2(wo[k0],     wo[k0 + 1]);
        f.w = packh2(wo[k0 + 8], wo[k0 + 9]);
        g_wcH[p] = f;
    } else {
        int b = bid - 64;
        int e = tid;
        __shared__ __align__(16) float s_src[D_];
        s_src[tid] = src[b * D_ + tid];
        __syncthreads();
        const float4* w4 = (const float4*)(Wq + (size_t)e * D_);
        const float4* s4 = (const float4*)s_src;
        float acc = 0.f;
#pragma unroll 8
        for (int i = 0; i < D_ / 4; ++i) {
            float4 wv = w4[i], xv = s4[i];
            acc += wv.x * xv.x + wv.y * xv.y + wv.z * xv.z + wv.w * xv.w;
        }
        g_wq[b * D_ + e] = acc + bq[e];
    }
}

// ============================================================
// Kernel 2: fused scores, fp16 m16n8k16, double-buffered (R7 structure).
// Also writes fp16 copy of memory_bank to g_mbH.
// grid (S/64, B), block 512 (2wr x 8wc). Warp tile m32 x n64.
// ============================================================
#define A_U32 1024                  // uint32 per A buffer
#define B_U32 8192                  // uint32 per B buffer
#define OF_AS   0
#define OF_BS   (2 * A_U32)
#define OF_WQ   (OF_BS + 2 * B_U32)
#define OF_V    (OF_WQ + D_)
#define OF_PART (OF_V + D_)
#define SMEM_U32 (OF_PART + TM * 8)
#define SMEM_BYTES (SMEM_U32 * 4)

__global__ void __launch_bounds__(512, 1)
scores_kernel(const float* __restrict__ mb, const float* __restrict__ vvec) {
    extern __shared__ __align__(16) uint32_t sm[];
    uint32_t* As = sm + OF_AS;
    float* swq   = (float*)(sm + OF_WQ);
    float* sv    = (float*)(sm + OF_V);
    float* spart = (float*)(sm + OF_PART);

    const int b   = blockIdx.y;
    const int s0  = blockIdx.x * TM;
    const int tid = threadIdx.x;
    const int wid = tid >> 5, lane = tid & 31;
    const int g = lane >> 2, t = lane & 3;
    const int wr = wid >> 3, wc = wid & 7;
    const int m0 = wr * 32, n0 = wc * 64;

    for (int i = tid; i < D_; i += 512) {
        swq[i] = g_wq[b * D_ + i];
        sv[i]  = vvec[i];
    }

    // A staging: thread -> (row = tid>>3, 4 k at koff=(tid&7)*4)
    const int am   = tid >> 3;
    const int koff = (tid & 7) * 4;
    const size_t arow = (size_t)b * S_ * D_ + (size_t)(s0 + am) * D_ + koff;
    const float* a_gbase = mb + arow;
    __half* h_base = g_mbH + arow;
    const uint32_t sbase = smem_u32(sm);
    int i0;
    {
        int kk = koff >> 4;
        int tt = (koff & 7) >> 1;
        int kq = (koff & 15) >> 3;
        int gg = am & 7, pm = (am >> 3) & 1, awr = (am >> 5) & 1, mt = (am >> 4) & 1;
        i0 = ((kk * 2 + awr) * 2 + mt) * 128 + (gg * 4 + tt) * 4 + (kq * 2 + pm);
    }

    float acc[2][8][4];
#pragma unroll
    for (int mt = 0; mt < 2; ++mt)
#pragma unroll
        for (int j = 0; j < 8; ++j)
#pragma unroll
            for (int q = 0; q < 4; ++q) acc[mt][j][q] = 0.f;

#define STAGE_B(kb_, buf_) do {                                            \
        const uint4* bsrc4 = g_wcH + (kb_) * 2048;                         \
        uint32_t bdst = sbase + (OF_BS + (buf_) * B_U32) * 4;              \
        _Pragma("unroll")                                                  \
        for (int c = 0; c < 4; ++c) {                                      \
            int fi = tid + c * 512;                                        \
            cp_async16(bdst + fi * 16, bsrc4 + fi);                        \
        }                                                                  \
    } while (0)

    // ---- prologue: stage tile 0 ----
    {
        STAGE_B(0, 0);
        asm volatile("cp.async.commit_group;" ::: "memory");
        float4 av = *(const float4*)a_gbase;
        uint2 hp = make_uint2(packh2(av.x, av.y), packh2(av.z, av.w));
        As[i0]     = hp.x;
        As[i0 + 4] = hp.y;
        *(uint2*)h_base = hp;     // fp16 side-channel
    }

#pragma unroll 1
    for (int kb = 0; kb < NKT; ++kb) {
        const int cur = kb & 1;
        float4 av;
        if (kb < NKT - 1) {
            av = *(const float4*)(a_gbase + (kb + 1) * TK);
            STAGE_B(kb + 1, cur ^ 1);
            asm volatile("cp.async.commit_group;" ::: "memory");
            asm volatile("cp.async.wait_group 1;" ::: "memory");
        } else {
            asm volatile("cp.async.wait_group 0;" ::: "memory");
        }
        __syncthreads();

        const uint32_t* Ac = As + cur * A_U32;
        const uint4* Bc = (const uint4*)(sm + OF_BS + cur * B_U32);
#pragma unroll
        for (int kk = 0; kk < 2; ++kk) {
            uint32_t a[2][4];
#pragma unroll
            for (int mt = 0; mt < 2; ++mt) {
                uint4 af = *(const uint4*)(Ac + ((kk * 2 + wr) * 2 + mt) * 128 + lane * 4);
                a[mt][0] = af.x; a[mt][1] = af.y; a[mt][2] = af.z; a[mt][3] = af.w;
            }
            const uint4* brow = Bc + ((kk * 8 + wc) * 4) * 32 + lane;
#pragma unroll
            for (int j2 = 0; j2 < 4; ++j2) {
                uint4 bf = brow[j2 * 32];
                mma_fp16(acc[0][j2 * 2],     a[0], bf.x, bf.y);
                mma_fp16(acc[1][j2 * 2],     a[1], bf.x, bf.y);
                mma_fp16(acc[0][j2 * 2 + 1], a[0], bf.z, bf.w);
                mma_fp16(acc[1][j2 * 2 + 1], a[1], bf.z, bf.w);
            }
        }

        if (kb < NKT - 1) {
            uint32_t* Ad = As + (cur ^ 1) * A_U32;
            uint2 hp = make_uint2(packh2(av.x, av.y), packh2(av.z, av.w));
            Ad[i0]     = hp.x;
            Ad[i0 + 4] = hp.y;
            *(uint2*)(h_base + (kb + 1) * TK) = hp;   // fp16 side-channel
        }
        __syncthreads();
    }

    // ---- epilogue: tanh + v dot, reduce ----
    float p[4] = {0.f, 0.f, 0.f, 0.f};
#pragma unroll
    for (int mt = 0; mt < 2; ++mt)
#pragma unroll
        for (int j = 0; j < 8; ++j) {
            const int c = n0 + j * 8 + 2 * t;
            const float v0 = sv[c], v1 = sv[c + 1];
            const float w0 = swq[c], w1 = swq[c + 1];
            p[mt * 2 + 0] += fast_tanh(w0 + acc[mt][j][0]) * v0 +
                             fast_tanh(w1 + acc[mt][j][1]) * v1;
            p[mt * 2 + 1] += fast_tanh(w0 + acc[mt][j][2]) * v0 +
                             fast_tanh(w1 + acc[mt][j][3]) * v1;
        }
#pragma unroll
    for (int q = 0; q < 4; ++q) {
        p[q] += __shfl_xor_sync(0xFFFFFFFFu, p[q], 1);
        p[q] += __shfl_xor_sync(0xFFFFFFFFu, p[q], 2);
    }
    if (t == 0) {
#pragma unroll
        for (int mt = 0; mt < 2; ++mt) {
            spart[(m0 + mt * 16 + g) * 8 + wc]     = p[mt * 2 + 0];
            spart[(m0 + mt * 16 + g + 8) * 8 + wc] = p[mt * 2 + 1];
        }
    }
    __syncthreads();
    if (tid < TM) {
        float s = 0.f;
#pragma unroll
        for (int w = 0; w < 8; ++w) s += spart[tid * 8 + w];
        g_scores[b * S_ + s0 + tid] = s;
    }
}

// ============================================================
// Kernel 3: masked softmax stats. grid B, block 1024
// ============================================================
__global__ void stats_kernel(const void* __restrict__ lens) {
    __shared__ float red[1024];
    int b = blockIdx.x, tid = threadIdx.x;
    int len = load_len(lens, b);

    float m = -3.4e38f;
    for (int s = tid; s < S_; s += 1024)
        if (s < len) m = fmaxf(m, g_scores[b * S_ + s]);
    red[tid] = m;
    __syncthreads();
    for (int o = 512; o > 0; o >>= 1) {
        if (tid < o) red[tid] = fmaxf(red[tid], red[tid + o]);
        __syncthreads();
    }
    m = red[0];
    __syncthreads();

    float sum = 0.f;
    for (int s = tid; s < S_; s += 1024)
        if (s < len) sum += __expf(g_scores[b * S_ + s] - m);
    red[tid] = sum;
    __syncthreads();
    for (int o = 512; o > 0; o >>= 1) {
        if (tid < o) red[tid] += red[tid + o];
        __syncthreads();
    }
    if (tid == 0) { g_stats[2 * b] = m; g_stats[2 * b + 1] = red[0]; }
}

// ============================================================
// Kernel 4a: context partials from fp16 mb copy.
// grid (16, B): x = dch(2) + 2*sch(8). block 128. Each thread: 2 cols (half2).
// ============================================================
__global__ void context_part_kernel(const void* __restrict__ lens,
                                    float* __restrict__ out) {
    __shared__ float w[256];
    int b = blockIdx.y, tid = threadIdx.x;
    int dch = blockIdx.x & 1, sch = blockIdx.x >> 1;
    int len = load_len(lens, b);
    float m = g_stats[2 * b];
    float inv = __fdividef(1.f, g_stats[2 * b + 1]);

    int sbase = sch * 256;
    for (int i = tid; i < 256; i += 128) {
        int s = sbase + i;
        w[i] = (s < len) ? __expf(g_scores[b * S_ + s] - m) * inv : 0.f;
    }
    __syncthreads();

    if (dch == 0) {
        float* align_out = out + B_ * D_;
        for (int i = tid; i < 256; i += 128) align_out[b * S_ + sbase + i] = w[i];
    }

    int d2 = dch * 256 + tid * 2;
    const __half2* p = (const __half2*)(g_mbH + (size_t)b * S_ * D_ +
                                        (size_t)sbase * D_ + d2);
    float acc0 = 0.f, acc1 = 0.f;
#pragma unroll 8
    for (int i = 0; i < 256; ++i) {
        float2 h = __half22float2(p[(size_t)i * (D_ / 2)]);
        acc0 += w[i] * h.x;
        acc1 += w[i] * h.y;
    }
    g_ctx[sch][b * D_ + d2]     = acc0;
    g_ctx[sch][b * D_ + d2 + 1] = acc1;
}

// ============================================================
// Kernel 4b: combine context partials. grid B, block 128
// ============================================================
__global__ void combine_kernel(float* __restrict__ out) {
    int b = blockIdx.x, tid = threadIdx.x;
    for (int d = tid; d < D_; d += 128) {
        int i = b * D_ + d;
        float s = 0.f;
#pragma unroll
        for (int c = 0; c < NSCH; ++c) s += g_ctx[c][i];
        out[i] = s;
    }
}

// ============================================================
extern "C" void kernel_launch(void* const* d_in, const int* in_sizes, int n_in,
                              void* d_out, int out_size) {
    const float* source = (const float*)d_in[0];
    const float* mb     = (const float*)d_in[1];
    const void*  lens   = (const void*)d_in[2];
    const float* Wq     = (const float*)d_in[3];
    const float* bq     = (const float*)d_in[4];
    const float* Wc     = (const float*)d_in[5];
    const float* v      = (const float*)d_in[6];
    float*       out    = (float*)d_out;

    cudaFuncSetAttribute(scores_kernel,
                         cudaFuncAttributeMaxDynamicSharedMemorySize, SMEM_BYTES);

    prep_kernel<<<128, 512>>>(Wc, source, Wq, bq);
    scores_kernel<<<dim3(S_ / TM, B_), 512, SMEM_BYTES>>>(mb, v);
    stats_kernel<<<B_, 1024>>>(lens);
    context_part_kernel<<<dim3(16, B_), 128>>>(lens, out);
    combine_kernel<<<B_, 128>>>(out);
}

// round 10
// speedup vs baseline: 1.2813x; 1.2813x over previous
#include <cuda_runtime.h>
#include <cuda_fp16.h>
#include <cstdint>

#define B_ 64
#define S_ 2048
#define D_ 512

#define TM 64            // M rows per CTA
#define TK 32            // K per stage tile
#define NKT (D_ / TK)    // 16 k-tiles
#define NSCH 8           // context S-chunks

// ---------------- scratch globals ----------------
__device__ float g_wq[B_ * D_];
__device__ float g_scores[B_ * S_];
__device__ float g_stats[2 * B_];
__device__ float g_ctx[NSCH][B_ * D_];
// Wc as fp16 in m16n8k16-fragment order
__device__ __align__(16) uint4 g_wcH[NKT * 2048];
// fp16 copy of memory_bank, written by scores_kernel as a side effect (134 MB)
__device__ __align__(16) __half g_mbH[(size_t)B_ * S_ * D_];

// ---------------- helpers ----------------
__device__ __forceinline__ float fast_tanh(float x) {
    float xc = fminf(fmaxf(x, -15.f), 15.f);
    float e = __expf(2.f * xc);
    return __fdividef(e - 1.f, e + 1.f);
}
// memory_lengths dtype sniff (int64 vs int32): word[1]==0 iff int64 (LE)
__device__ __forceinline__ int load_len(const void* lens, int b) {
    const int* p32 = (const int*)lens;
    if (p32[1] == 0) return (int)((const long long*)lens)[b];
    return p32[b];
}
__device__ __forceinline__ uint32_t smem_u32(const void* p) {
    uint32_t a;
    asm("{ .reg .u64 t; cvta.to.shared.u64 t, %1; cvt.u32.u64 %0, t; }" : "=r"(a) : "l"(p));
    return a;
}
__device__ __forceinline__ void cp_async16(uint32_t dst, const void* src) {
    asm volatile("cp.async.cg.shared.global [%0], [%1], 16;" :: "r"(dst), "l"(src));
}
__device__ __forceinline__ uint32_t packh2(float a, float b) {
    __half2 h = __floats2half2_rn(a, b);
    return *(uint32_t*)&h;
}
// evict-first streaming store: don't pollute L2 (protects resident g_wcH)
__device__ __forceinline__ void stg_cs_u64(void* p, uint2 v) {
    asm volatile("st.global.cs.v2.u32 [%0], {%1, %2};"
                 :: "l"(p), "r"(v.x), "r"(v.y) : "memory");
}
__device__ __forceinline__ void mma_fp16(float* c, const uint32_t* a,
                                         uint32_t b0, uint32_t b1) {
    asm volatile(
        "mma.sync.aligned.m16n8k16.row.col.f32.f16.f16.f32 "
        "{%0,%1,%2,%3}, {%4,%5,%6,%7}, {%8,%9}, {%0,%1,%2,%3};"
        : "+f"(c[0]), "+f"(c[1]), "+f"(c[2]), "+f"(c[3])
        : "r"(a[0]), "r"(a[1]), "r"(a[2]), "r"(a[3]), "r"(b0), "r"(b1));
}

// ============================================================
// Kernel 0: fused prep (Wc -> fp16 fragment order) + wq GEMV.
// grid 128, block 512. bid<64: prep; bid>=64: wq for batch bid-64.
// ============================================================
__global__ void prep_kernel(const float* __restrict__ Wc,
                            const float* __restrict__ src,
                            const float* __restrict__ Wq,
                            const float* __restrict__ bq) {
    int bid = blockIdx.x, tid = threadIdx.x;
    if (bid < 64) {
        int p = bid * 512 + tid;     // 32768 uint4
        int lane = p & 31;
        int j2   = (p >> 5) & 3;
        int wc   = (p >> 7) & 7;
        int kk   = (p >> 10) & 1;
        int kb   = (p >> 11) & 15;
        int g = lane >> 2, t = lane & 3;
        int ne = wc * 64 + j2 * 16 + g;
        int no = ne + 8;
        int k0 = kb * 32 + kk * 16 + 2 * t;
        const float* we = Wc + (size_t)ne * D_;
        const float* wo = Wc + (size_t)no * D_;
        uint4 f;
        f.x = packh2(we[k0],     we[k0 + 1]);
        f.y = packh2(we[k0 + 8], we[k0 + 9]);
        f.z = packh2(wo[k0],     wo[k0 + 1]);
        f.w = packh2(wo[k0 + 8], wo[k0 + 9]);
        g_wcH[p] = f;
    } else {
        int b = bid - 64;
        int e = tid;
        __shared__ __align__(16) float s_src[D_];
        s_src[tid] = src[b * D_ + tid];
        __syncthreads();
        const float4* w4 = (const float4*)(Wq + (size_t)e * D_);
        const float4* s4 = (const float4*)s_src;
        float acc = 0.f;
#pragma unroll 8
        for (int i = 0; i < D_ / 4; ++i) {
            float4 wv = w4[i], xv = s4[i];
            acc += wv.x * xv.x + wv.y * xv.y + wv.z * xv.z + wv.w * xv.w;
        }
        g_wq[b * D_ + e] = acc + bq[e];
    }
}

// ============================================================
// Kernel 2: fused scores, fp16 m16n8k16, double-buffered.
// Writes fp16 copy of memory_bank to g_mbH with .cs (evict-first).
// grid (S/64, B), block 512 (2wr x 8wc). Warp tile m32 x n64.
// ============================================================
#define A_U32 1024                  // uint32 per A buffer
#define B_U32 8192                  // uint32 per B buffer
#define OF_AS   0
#define OF_BS   (2 * A_U32)
#define OF_WQ   (OF_BS + 2 * B_U32)
#define OF_V    (OF_WQ + D_)
#define OF_PART (OF_V + D_)
#define SMEM_U32 (OF_PART + TM * 8)
#define SMEM_BYTES (SMEM_U32 * 4)

__global__ void __launch_bounds__(512, 1)
scores_kernel(const float* __restrict__ mb, const float* __restrict__ vvec) {
    extern __shared__ __align__(16) uint32_t sm[];
    uint32_t* As = sm + OF_AS;
    float* swq   = (float*)(sm + OF_WQ);
    float* sv    = (float*)(sm + OF_V);
    float* spart = (float*)(sm + OF_PART);

    const int b   = blockIdx.y;
    const int s0  = blockIdx.x * TM;
    const int tid = threadIdx.x;
    const int wid = tid >> 5, lane = tid & 31;
    const int g = lane >> 2, t = lane & 3;
    const int wr = wid >> 3, wc = wid & 7;
    const int m0 = wr * 32, n0 = wc * 64;

    for (int i = tid; i < D_; i += 512) {
        swq[i] = g_wq[b * D_ + i];
        sv[i]  = vvec[i];
    }

    // A staging: thread -> (row = tid>>3, 4 k at koff=(tid&7)*4)
    const int am   = tid >> 3;
    const int koff = (tid & 7) * 4;
    const size_t arow = (size_t)b * S_ * D_ + (size_t)(s0 + am) * D_ + koff;
    const float* a_gbase = mb + arow;
    __half* h_base = g_mbH + arow;
    const uint32_t sbase = smem_u32(sm);
    int i0;
    {
        int kk = koff >> 4;
        int tt = (koff & 7) >> 1;
        int kq = (koff & 15) >> 3;
        int gg = am & 7, pm = (am >> 3) & 1, awr = (am >> 5) & 1, mt = (am >> 4) & 1;
        i0 = ((kk * 2 + awr) * 2 + mt) * 128 + (gg * 4 + tt) * 4 + (kq * 2 + pm);
    }

    float acc[2][8][4];
#pragma unroll
    for (int mt = 0; mt < 2; ++mt)
#pragma unroll
        for (int j = 0; j < 8; ++j)
#pragma unroll
            for (int q = 0; q < 4; ++q) acc[mt][j][q] = 0.f;

#define STAGE_B(kb_, buf_) do {                                            \
        const uint4* bsrc4 = g_wcH + (kb_) * 2048;                         \
        uint32_t bdst = sbase + (OF_BS + (buf_) * B_U32) * 4;              \
        _Pragma("unroll")                                                  \
        for (int c = 0; c < 4; ++c) {                                      \
            int fi = tid + c * 512;                                        \
            cp_async16(bdst + fi * 16, bsrc4 + fi);                        \
        }                                                                  \
    } while (0)

    // ---- prologue: stage tile 0 ----
    {
        STAGE_B(0, 0);
        asm volatile("cp.async.commit_group;" ::: "memory");
        float4 av = *(const float4*)a_gbase;
        uint2 hp = make_uint2(packh2(av.x, av.y), packh2(av.z, av.w));
        As[i0]     = hp.x;
        As[i0 + 4] = hp.y;
        stg_cs_u64(h_base, hp);     // fp16 side-channel, evict-first
    }

#pragma unroll 1
    for (int kb = 0; kb < NKT; ++kb) {
        const int cur = kb & 1;
        float4 av;
        if (kb < NKT - 1) {
            av = *(const float4*)(a_gbase + (kb + 1) * TK);
            STAGE_B(kb + 1, cur ^ 1);
            asm volatile("cp.async.commit_group;" ::: "memory");
            asm volatile("cp.async.wait_group 1;" ::: "memory");
        } else {
            asm volatile("cp.async.wait_group 0;" ::: "memory");
        }
        __syncthreads();

        const uint32_t* Ac = As + cur * A_U32;
        const uint4* Bc = (const uint4*)(sm + OF_BS + cur * B_U32);
#pragma unroll
        for (int kk = 0; kk < 2; ++kk) {
            uint32_t a[2][4];
#pragma unroll
            for (int mt = 0; mt < 2; ++mt) {
                uint4 af = *(const uint4*)(Ac + ((kk * 2 + wr) * 2 + mt) * 128 + lane * 4);
                a[mt][0] = af.x; a[mt][1] = af.y; a[mt][2] = af.z; a[mt][3] = af.w;
            }
            const uint4* brow = Bc + ((kk * 8 + wc) * 4) * 32 + lane;
#pragma unroll
            for (int j2 = 0; j2 < 4; ++j2) {
                uint4 bf = brow[j2 * 32];
                mma_fp16(acc[0][j2 * 2],     a[0], bf.x, bf.y);
                mma_fp16(acc[1][j2 * 2],     a[1], bf.x, bf.y);
                mma_fp16(acc[0][j2 * 2 + 1], a[0], bf.z, bf.w);
                mma_fp16(acc[1][j2 * 2 + 1], a[1], bf.z, bf.w);
            }
        }

        if (kb < NKT - 1) {
            uint32_t* Ad = As + (cur ^ 1) * A_U32;
            uint2 hp = make_uint2(packh2(av.x, av.y), packh2(av.z, av.w));
            Ad[i0]     = hp.x;
            Ad[i0 + 4] = hp.y;
            stg_cs_u64(h_base + (kb + 1) * TK, hp);   // evict-first
        }
        __syncthreads();
    }

    // ---- epilogue: tanh + v dot, reduce ----
    float p[4] = {0.f, 0.f, 0.f, 0.f};
#pragma unroll
    for (int mt = 0; mt < 2; ++mt)
#pragma unroll
        for (int j = 0; j < 8; ++j) {
            const int c = n0 + j * 8 + 2 * t;
            const float v0 = sv[c], v1 = sv[c + 1];
            const float w0 = swq[c], w1 = swq[c + 1];
            p[mt * 2 + 0] += fast_tanh(w0 + acc[mt][j][0]) * v0 +
                             fast_tanh(w1 + acc[mt][j][1]) * v1;
            p[mt * 2 + 1] += fast_tanh(w0 + acc[mt][j][2]) * v0 +
                             fast_tanh(w1 + acc[mt][j][3]) * v1;
        }
#pragma unroll
    for (int q = 0; q < 4; ++q) {
        p[q] += __shfl_xor_sync(0xFFFFFFFFu, p[q], 1);
        p[q] += __shfl_xor_sync(0xFFFFFFFFu, p[q], 2);
    }
    if (t == 0) {
#pragma unroll
        for (int mt = 0; mt < 2; ++mt) {
            spart[(m0 + mt * 16 + g) * 8 + wc]     = p[mt * 2 + 0];
            spart[(m0 + mt * 16 + g + 8) * 8 + wc] = p[mt * 2 + 1];
        }
    }
    __syncthreads();
    if (tid < TM) {
        float s = 0.f;
#pragma unroll
        for (int w = 0; w < 8; ++w) s += spart[tid * 8 + w];
        g_scores[b * S_ + s0 + tid] = s;
    }
}

// ============================================================
// Kernel 3: masked softmax stats. grid B, block 1024
// ============================================================
__global__ void stats_kernel(const void* __restrict__ lens) {
    __shared__ float red[1024];
    int b = blockIdx.x, tid = threadIdx.x;
    int len = load_len(lens, b);

    float m = -3.4e38f;
    for (int s = tid; s < S_; s += 1024)
        if (s < len) m = fmaxf(m, g_scores[b * S_ + s]);
    red[tid] = m;
    __syncthreads();
    for (int o = 512; o > 0; o >>= 1) {
        if (tid < o) red[tid] = fmaxf(red[tid], red[tid + o]);
        __syncthreads();
    }
    m = red[0];
    __syncthreads();

    float sum = 0.f;
    for (int s = tid; s < S_; s += 1024)
        if (s < len) sum += __expf(g_scores[b * S_ + s] - m);
    red[tid] = sum;
    __syncthreads();
    for (int o = 512; o > 0; o >>= 1) {
        if (tid < o) red[tid] += red[tid + o];
        __syncthreads();
    }
    if (tid == 0) { g_stats[2 * b] = m; g_stats[2 * b + 1] = red[0]; }
}

// ============================================================
// Kernel 4a: context partials from fp16 mb copy.
// grid (16, B): x = dch(2) + 2*sch(8). block 128. Each thread: 2 cols (half2).
// ============================================================
__global__ void context_part_kernel(const void* __restrict__ lens,
                                    float* __restrict__ out) {
    __shared__ float w[256];
    int b = blockIdx.y, tid = threadIdx.x;
    int dch = blockIdx.x & 1, sch = blockIdx.x >> 1;
    int len = load_len(lens, b);
    float m = g_stats[2 * b];
    float inv = __fdividef(1.f, g_stats[2 * b + 1]);

    int sbase = sch * 256;
    for (int i = tid; i < 256; i += 128) {
        int s = sbase + i;
        w[i] = (s < len) ? __expf(g_scores[b * S_ + s] - m) * inv : 0.f;
    }
    __syncthreads();

    if (dch == 0) {
        float* align_out = out + B_ * D_;
        for (int i = tid; i < 256; i += 128) align_out[b * S_ + sbase + i] = w[i];
    }

    int d2 = dch * 256 + tid * 2;
    const __half2* p = (const __half2*)(g_mbH + (size_t)b * S_ * D_ +
                                        (size_t)sbase * D_ + d2);
    float acc0 = 0.f, acc1 = 0.f;
#pragma unroll 8
    for (int i = 0; i < 256; ++i) {
        float2 h = __half22float2(p[(size_t)i * (D_ / 2)]);
        acc0 += w[i] * h.x;
        acc1 += w[i] * h.y;
    }
    g_ctx[sch][b * D_ + d2]     = acc0;
    g_ctx[sch][b * D_ + d2 + 1] = acc1;
}

// ============================================================
// Kernel 4b: combine context partials. grid B, block 128
// ============================================================
__global__ void combine_kernel(float* __restrict__ out) {
    int b = blockIdx.x, tid = threadIdx.x;
    for (int d = tid; d < D_; d += 128) {
        int i = b * D_ + d;
        float s = 0.f;
#pragma unroll
        for (int c = 0; c < NSCH; ++c) s += g_ctx[c][i];
        out[i] = s;
    }
}

// ============================================================
extern "C" void kernel_launch(void* const* d_in, const int* in_sizes, int n_in,
                              void* d_out, int out_size) {
    const float* source = (const float*)d_in[0];
    const float* mb     = (const float*)d_in[1];
    const void*  lens   = (const void*)d_in[2];
    const float* Wq     = (const float*)d_in[3];
    const float* bq     = (const float*)d_in[4];
    const float* Wc     = (const float*)d_in[5];
    const float* v      = (const float*)d_in[6];
    float*       out    = (float*)d_out;

    cudaFuncSetAttribute(scores_kernel,
                         cudaFuncAttributeMaxDynamicSharedMemorySize, SMEM_BYTES);

    prep_kernel<<<128, 512>>>(Wc, source, Wq, bq);
    scores_kernel<<<dim3(S_ / TM, B_), 512, SMEM_BYTES>>>(mb, v);
    stats_kernel<<<B_, 1024>>>(lens);
    context_part_kernel<<<dim3(16, B_), 128>>>(lens, out);
    combine_kernel<<<B_, 128>>>(out);
}

// round 11
// speedup vs baseline: 1.8234x; 1.4231x over previous
#include <cuda_runtime.h>
#include <cuda_fp16.h>
#include <cstdint>

#define B_ 64
#define S_ 2048
#define D_ 512

#define TM 64            // M rows per CTA
#define TK 32            // K per stage tile
#define NKT (D_ / TK)    // 16 k-tiles
#define NSCH 8           // context S-chunks

// ---------------- scratch globals ----------------
__device__ float g_wq[B_ * D_];
__device__ float g_scores[B_ * S_];
__device__ float g_stats[2 * B_];
__device__ float g_ctx[NSCH][B_ * D_];
// Wc as fp16 in m16n8k16-fragment order
__device__ __align__(16) uint4 g_wcH[NKT * 2048];

// ---------------- helpers ----------------
__device__ __forceinline__ float fast_tanh(float x) {
    float xc = fminf(fmaxf(x, -15.f), 15.f);
    float e = __expf(2.f * xc);
    return __fdividef(e - 1.f, e + 1.f);
}
// memory_lengths dtype sniff (int64 vs int32): word[1]==0 iff int64 (LE)
__device__ __forceinline__ int load_len(const void* lens, int b) {
    const int* p32 = (const int*)lens;
    if (p32[1] == 0) return (int)((const long long*)lens)[b];
    return p32[b];
}
__device__ __forceinline__ uint32_t smem_u32(const void* p) {
    uint32_t a;
    asm("{ .reg .u64 t; cvta.to.shared.u64 t, %1; cvt.u32.u64 %0, t; }" : "=r"(a) : "l"(p));
    return a;
}
__device__ __forceinline__ void cp_async16(uint32_t dst, const void* src) {
    asm volatile("cp.async.cg.shared.global [%0], [%1], 16;" :: "r"(dst), "l"(src));
}
__device__ __forceinline__ uint32_t packh2(float a, float b) {
    __half2 h = __floats2half2_rn(a, b);
    return *(uint32_t*)&h;
}
__device__ __forceinline__ void mma_fp16(float* c, const uint32_t* a,
                                         uint32_t b0, uint32_t b1) {
    asm volatile(
        "mma.sync.aligned.m16n8k16.row.col.f32.f16.f16.f32 "
        "{%0,%1,%2,%3}, {%4,%5,%6,%7}, {%8,%9}, {%0,%1,%2,%3};"
        : "+f"(c[0]), "+f"(c[1]), "+f"(c[2]), "+f"(c[3])
        : "r"(a[0]), "r"(a[1]), "r"(a[2]), "r"(a[3]), "r"(b0), "r"(b1));
}

// ============================================================
// Kernel 0: fused prep (Wc -> fp16 fragment order) + wq GEMV.
// grid 128, block 512. bid<64: prep; bid>=64: wq for batch bid-64.
// ============================================================
__global__ void prep_kernel(const float* __restrict__ Wc,
                            const float* __restrict__ src,
                            const float* __restrict__ Wq,
                            const float* __restrict__ bq) {
    int bid = blockIdx.x, tid = threadIdx.x;
    if (bid < 64) {
        int p = bid * 512 + tid;     // 32768 uint4
        int lane = p & 31;
        int j2   = (p >> 5) & 3;
        int wc   = (p >> 7) & 7;
        int kk   = (p >> 10) & 1;
        int kb   = (p >> 11) & 15;
        int g = lane >> 2, t = lane & 3;
        int ne = wc * 64 + j2 * 16 + g;
        int no = ne + 8;
        int k0 = kb * 32 + kk * 16 + 2 * t;
        const float* we = Wc + (size_t)ne * D_;
        const float* wo = Wc + (size_t)no * D_;
        uint4 f;
        f.x = packh2(we[k0],     we[k0 + 1]);
        f.y = packh2(we[k0 + 8], we[k0 + 9]);
        f.z = packh2(wo[k0],     wo[k0 + 1]);
        f.w = packh2(wo[k0 + 8], wo[k0 + 9]);
        g_wcH[p] = f;
    } else {
        int b = bid - 64;
        int e = tid;
        __shared__ __align__(16) float s_src[D_];
        s_src[tid] = src[b * D_ + tid];
        __syncthreads();
        const float4* w4 = (const float4*)(Wq + (size_t)e * D_);
        const float4* s4 = (const float4*)s_src;
        float acc = 0.f;
#pragma unroll 8
        for (int i = 0; i < D_ / 4; ++i) {
            float4 wv = w4[i], xv = s4[i];
            acc += wv.x * xv.x + wv.y * xv.y + wv.z * xv.z + wv.w * xv.w;
        }
        g_wq[b * D_ + e] = acc + bq[e];
    }
}

// ============================================================
// Kernel 2: fused scores, fp16 m16n8k16, double-buffered (R7 exact) +
// early exit for s-tiles entirely beyond memory_lengths[b].
// grid (S/64, B), block 512 (2wr x 8wc). Warp tile m32 x n64.
// ============================================================
#define A_U32 1024                  // uint32 per A buffer
#define B_U32 8192                  // uint32 per B buffer
#define OF_AS   0
#define OF_BS   (2 * A_U32)
#define OF_WQ   (OF_BS + 2 * B_U32)
#define OF_V    (OF_WQ + D_)
#define OF_PART (OF_V + D_)
#define SMEM_U32 (OF_PART + TM * 8)
#define SMEM_BYTES (SMEM_U32 * 4)

__global__ void __launch_bounds__(512, 1)
scores_kernel(const float* __restrict__ mb, const float* __restrict__ vvec,
              const void* __restrict__ lens) {
    const int b  = blockIdx.y;
    const int s0 = blockIdx.x * TM;
    // masked rows are never consumed downstream: skip dead tiles
    if (s0 >= load_len(lens, b)) return;

    extern __shared__ __align__(16) uint32_t sm[];
    uint32_t* As = sm + OF_AS;
    float* swq   = (float*)(sm + OF_WQ);
    float* sv    = (float*)(sm + OF_V);
    float* spart = (float*)(sm + OF_PART);

    const int tid = threadIdx.x;
    const int wid = tid >> 5, lane = tid & 31;
    const int g = lane >> 2, t = lane & 3;
    const int wr = wid >> 3, wc = wid & 7;
    const int m0 = wr * 32, n0 = wc * 64;

    for (int i = tid; i < D_; i += 512) {
        swq[i] = g_wq[b * D_ + i];
        sv[i]  = vvec[i];
    }

    // A staging: thread -> (row = tid>>3, 4 k at koff=(tid&7)*4)
    const int am   = tid >> 3;
    const int koff = (tid & 7) * 4;
    const float* a_gbase = mb + (size_t)b * S_ * D_ + (size_t)(s0 + am) * D_ + koff;
    const uint32_t sbase = smem_u32(sm);
    int i0;
    {
        int kk = koff >> 4;
        int tt = (koff & 7) >> 1;
        int kq = (koff & 15) >> 3;
        int gg = am & 7, pm = (am >> 3) & 1, awr = (am >> 5) & 1, mt = (am >> 4) & 1;
        i0 = ((kk * 2 + awr) * 2 + mt) * 128 + (gg * 4 + tt) * 4 + (kq * 2 + pm);
    }

    float acc[2][8][4];
#pragma unroll
    for (int mt = 0; mt < 2; ++mt)
#pragma unroll
        for (int j = 0; j < 8; ++j)
#pragma unroll
            for (int q = 0; q < 4; ++q) acc[mt][j][q] = 0.f;

#define STAGE_B(kb_, buf_) do {                                            \
        const uint4* bsrc4 = g_wcH + (kb_) * 2048;                         \
        uint32_t bdst = sbase + (OF_BS + (buf_) * B_U32) * 4;              \
        _Pragma("unroll")                                                  \
        for (int c = 0; c < 4; ++c) {                                      \
            int fi = tid + c * 512;                                        \
            cp_async16(bdst + fi * 16, bsrc4 + fi);                        \
        }                                                                  \
    } while (0)

    // ---- prologue: stage tile 0 ----
    {
        STAGE_B(0, 0);
        asm volatile("cp.async.commit_group;" ::: "memory");
        float4 av = *(const float4*)a_gbase;
        As[i0]     = packh2(av.x, av.y);
        As[i0 + 4] = packh2(av.z, av.w);
    }

#pragma unroll 1
    for (int kb = 0; kb < NKT; ++kb) {
        const int cur = kb & 1;
        float4 av;
        if (kb < NKT - 1) {
            av = *(const float4*)(a_gbase + (kb + 1) * TK);
            STAGE_B(kb + 1, cur ^ 1);
            asm volatile("cp.async.commit_group;" ::: "memory");
            asm volatile("cp.async.wait_group 1;" ::: "memory");
        } else {
            asm volatile("cp.async.wait_group 0;" ::: "memory");
        }
        __syncthreads();

        const uint32_t* Ac = As + cur * A_U32;
        const uint4* Bc = (const uint4*)(sm + OF_BS + cur * B_U32);
#pragma unroll
        for (int kk = 0; kk < 2; ++kk) {
            uint32_t a[2][4];
#pragma unroll
            for (int mt = 0; mt < 2; ++mt) {
                uint4 af = *(const uint4*)(Ac + ((kk * 2 + wr) * 2 + mt) * 128 + lane * 4);
                a[mt][0] = af.x; a[mt][1] = af.y; a[mt][2] = af.z; a[mt][3] = af.w;
            }
            const uint4* brow = Bc + ((kk * 8 + wc) * 4) * 32 + lane;
#pragma unroll
            for (int j2 = 0; j2 < 4; ++j2) {
                uint4 bf = brow[j2 * 32];
                mma_fp16(acc[0][j2 * 2],     a[0], bf.x, bf.y);
                mma_fp16(acc[1][j2 * 2],     a[1], bf.x, bf.y);
                mma_fp16(acc[0][j2 * 2 + 1], a[0], bf.z, bf.w);
                mma_fp16(acc[1][j2 * 2 + 1], a[1], bf.z, bf.w);
            }
        }

        if (kb < NKT - 1) {
            uint32_t* Ad = As + (cur ^ 1) * A_U32;
            Ad[i0]     = packh2(av.x, av.y);
            Ad[i0 + 4] = packh2(av.z, av.w);
        }
        __syncthreads();
    }

    // ---- epilogue: tanh + v dot, reduce ----
    float p[4] = {0.f, 0.f, 0.f, 0.f};
#pragma unroll
    for (int mt = 0; mt < 2; ++mt)
#pragma unroll
        for (int j = 0; j < 8; ++j) {
            const int c = n0 + j * 8 + 2 * t;
            const float v0 = sv[c], v1 = sv[c + 1];
            const float w0 = swq[c], w1 = swq[c + 1];
            p[mt * 2 + 0] += fast_tanh(w0 + acc[mt][j][0]) * v0 +
                             fast_tanh(w1 + acc[mt][j][1]) * v1;
            p[mt * 2 + 1] += fast_tanh(w0 + acc[mt][j][2]) * v0 +
                             fast_tanh(w1 + acc[mt][j][3]) * v1;
        }
#pragma unroll
    for (int q = 0; q < 4; ++q) {
        p[q] += __shfl_xor_sync(0xFFFFFFFFu, p[q], 1);
        p[q] += __shfl_xor_sync(0xFFFFFFFFu, p[q], 2);
    }
    if (t == 0) {
#pragma unroll
        for (int mt = 0; mt < 2; ++mt) {
            spart[(m0 + mt * 16 + g) * 8 + wc]     = p[mt * 2 + 0];
            spart[(m0 + mt * 16 + g + 8) * 8 + wc] = p[mt * 2 + 1];
        }
    }
    __syncthreads();
    if (tid < TM) {
        float s = 0.f;
#pragma unroll
        for (int w = 0; w < 8; ++w) s += spart[tid * 8 + w];
        g_scores[b * S_ + s0 + tid] = s;
    }
}

// ============================================================
// Kernel 3: masked softmax stats (loops clamped to len). grid B, block 1024
// ============================================================
__global__ void stats_kernel(const void* __restrict__ lens) {
    __shared__ float red[1024];
    int b = blockIdx.x, tid = threadIdx.x;
    int len = load_len(lens, b);

    float m = -3.4e38f;
    for (int s = tid; s < len; s += 1024)
        m = fmaxf(m, g_scores[b * S_ + s]);
    red[tid] = m;
    __syncthreads();
    for (int o = 512; o > 0; o >>= 1) {
        if (tid < o) red[tid] = fmaxf(red[tid], red[tid + o]);
        __syncthreads();
    }
    m = red[0];
    __syncthreads();

    float sum = 0.f;
    for (int s = tid; s < len; s += 1024)
        sum += __expf(g_scores[b * S_ + s] - m);
    red[tid] = sum;
    __syncthreads();
    for (int o = 512; o > 0; o >>= 1) {
        if (tid < o) red[tid] += red[tid + o];
        __syncthreads();
    }
    if (tid == 0) { g_stats[2 * b] = m; g_stats[2 * b + 1] = red[0]; }
}

// ============================================================
// Kernel 4a: context partials (fp32 mb, length-clamped).
// grid (32, B): x = dch(4) + 4*sch(8). block 128.
// ============================================================
__global__ void context_part_kernel(const float* __restrict__ mb,
                                    const void* __restrict__ lens,
                                    float* __restrict__ out) {
    __shared__ float w[256];
    int b = blockIdx.y, tid = threadIdx.x;
    int dch = blockIdx.x & 3, sch = blockIdx.x >> 2;
    int len = load_len(lens, b);
    int sbase = sch * 256;
    int d = dch * 128 + tid;

    if (sbase >= len) {   // dead chunk: zero partials + align, skip reads
        if (dch == 0) {
            float* align_out = out + B_ * D_;
            for (int i = tid; i < 256; i += 128) align_out[b * S_ + sbase + i] = 0.f;
        }
        g_ctx[sch][b * D_ + d] = 0.f;
        return;
    }

    float m = g_stats[2 * b];
    float inv = __fdividef(1.f, g_stats[2 * b + 1]);
    int cnt = min(256, len - sbase);

    for (int i = tid; i < 256; i += 128)
        w[i] = (i < cnt) ? __expf(g_scores[b * S_ + sbase + i] - m) * inv : 0.f;
    __syncthreads();

    if (dch == 0) {
        float* align_out = out + B_ * D_;
        for (int i = tid; i < 256; i += 128) align_out[b * S_ + sbase + i] = w[i];
    }

    const float* p = mb + (size_t)b * S_ * D_ + (size_t)sbase * D_ + d;
    float acc = 0.f;
#pragma unroll 4
    for (int i = 0; i < cnt; ++i) acc += w[i] * p[(size_t)i * D_];
    g_ctx[sch][b * D_ + d] = acc;
}

// ============================================================
// Kernel 4b: combine context partials. grid B, block 128
// ============================================================
__global__ void combine_kernel(float* __restrict__ out) {
    int b = blockIdx.x, tid = threadIdx.x;
    for (int d = tid; d < D_; d += 128) {
        int i = b * D_ + d;
        float s = 0.f;
#pragma unroll
        for (int c = 0; c < NSCH; ++c) s += g_ctx[c][i];
        out[i] = s;
    }
}

// ============================================================
extern "C" void kernel_launch(void* const* d_in, const int* in_sizes, int n_in,
                              void* d_out, int out_size) {
    const float* source = (const float*)d_in[0];
    const float* mb     = (const float*)d_in[1];
    const void*  lens   = (const void*)d_in[2];
    const float* Wq     = (const float*)d_in[3];
    const float* bq     = (const float*)d_in[4];
    const float* Wc     = (const float*)d_in[5];
    const float* v      = (const float*)d_in[6];
    float*       out    = (float*)d_out;

    cudaFuncSetAttribute(scores_kernel,
                         cudaFuncAttributeMaxDynamicSharedMemorySize, SMEM_BYTES);

    prep_kernel<<<128, 512>>>(Wc, source, Wq, bq);
    scores_kernel<<<dim3(S_ / TM, B_), 512, SMEM_BYTES>>>(mb, v, lens);
    stats_kernel<<<B_, 1024>>>(lens);
    context_part_kernel<<<dim3(32, B_), 128>>>(mb, lens, out);
    combine_kernel<<<B_, 128>>>(out);
}

// round 12
// speedup vs baseline: 1.8421x; 1.0103x over previous
#include <cuda_runtime.h>
#include <cuda_fp16.h>
#include <cstdint>

#define B_ 64
#define S_ 2048
#define D_ 512

#define TM 64            // M rows per CTA
#define TK 32            // K per stage tile
#define NKT (D_ / TK)    // 16 k-tiles
#define NSCH 8           // context S-chunks

// ---------------- scratch globals ----------------
__device__ float g_wq[B_ * D_];
__device__ float g_scores[B_ * S_];
__device__ float g_stats[2 * B_];
__device__ float g_ctx[NSCH][B_ * D_];
// Wc as fp16 in m16n8k16-fragment order
__device__ __align__(16) uint4 g_wcH[NKT * 2048];

// ---------------- helpers ----------------
__device__ __forceinline__ float fast_tanh(float x) {
    float xc = fminf(fmaxf(x, -15.f), 15.f);
    float e = __expf(2.f * xc);
    return __fdividef(e - 1.f, e + 1.f);
}
// memory_lengths dtype sniff (int64 vs int32): word[1]==0 iff int64 (LE)
__device__ __forceinline__ int load_len(const void* lens, int b) {
    const int* p32 = (const int*)lens;
    if (p32[1] == 0) return (int)((const long long*)lens)[b];
    return p32[b];
}
__device__ __forceinline__ uint32_t smem_u32(const void* p) {
    uint32_t a;
    asm("{ .reg .u64 t; cvta.to.shared.u64 t, %1; cvt.u32.u64 %0, t; }" : "=r"(a) : "l"(p));
    return a;
}
__device__ __forceinline__ void cp_async16(uint32_t dst, const void* src) {
    asm volatile("cp.async.cg.shared.global [%0], [%1], 16;" :: "r"(dst), "l"(src));
}
__device__ __forceinline__ uint32_t packh2(float a, float b) {
    __half2 h = __floats2half2_rn(a, b);
    return *(uint32_t*)&h;
}
__device__ __forceinline__ void mma_fp16(float* c, const uint32_t* a,
                                         uint32_t b0, uint32_t b1) {
    asm volatile(
        "mma.sync.aligned.m16n8k16.row.col.f32.f16.f16.f32 "
        "{%0,%1,%2,%3}, {%4,%5,%6,%7}, {%8,%9}, {%0,%1,%2,%3};"
        : "+f"(c[0]), "+f"(c[1]), "+f"(c[2]), "+f"(c[3])
        : "r"(a[0]), "r"(a[1]), "r"(a[2]), "r"(a[3]), "r"(b0), "r"(b1));
}

// ============================================================
// Kernel 0: fused prep (Wc -> fp16 fragment order) + wq GEMV.
// grid 128, block 512. bid<64: prep; bid>=64: wq for batch bid-64.
// ============================================================
__global__ void prep_kernel(const float* __restrict__ Wc,
                            const float* __restrict__ src,
                            const float* __restrict__ Wq,
                            const float* __restrict__ bq) {
    int bid = blockIdx.x, tid = threadIdx.x;
    if (bid < 64) {
        int p = bid * 512 + tid;     // 32768 uint4
        int lane = p & 31;
        int j2   = (p >> 5) & 3;
        int wc   = (p >> 7) & 7;
        int kk   = (p >> 10) & 1;
        int kb   = (p >> 11) & 15;
        int g = lane >> 2, t = lane & 3;
        int ne = wc * 64 + j2 * 16 + g;
        int no = ne + 8;
        int k0 = kb * 32 + kk * 16 + 2 * t;
        const float* we = Wc + (size_t)ne * D_;
        const float* wo = Wc + (size_t)no * D_;
        uint4 f;
        f.x = packh2(we[k0],     we[k0 + 1]);
        f.y = packh2(we[k0 + 8], we[k0 + 9]);
        f.z = packh2(wo[k0],     wo[k0 + 1]);
        f.w = packh2(wo[k0 + 8], wo[k0 + 9]);
        g_wcH[p] = f;
    } else {
        int b = bid - 64;
        int e = tid;
        __shared__ __align__(16) float s_src[D_];
        s_src[tid] = src[b * D_ + tid];
        __syncthreads();
        const float4* w4 = (const float4*)(Wq + (size_t)e * D_);
        const float4* s4 = (const float4*)s_src;
        float acc = 0.f;
#pragma unroll 8
        for (int i = 0; i < D_ / 4; ++i) {
            float4 wv = w4[i], xv = s4[i];
            acc += wv.x * xv.x + wv.y * xv.y + wv.z * xv.z + wv.w * xv.w;
        }
        g_wq[b * D_ + e] = acc + bq[e];
    }
}

// ============================================================
// Kernel 2: fused scores, fp16 m16n8k16, double-buffered +
// early exit for s-tiles entirely beyond memory_lengths[b].
// grid (S/64, B), block 512 (2wr x 8wc). Warp tile m32 x n64.
// ============================================================
#define A_U32 1024                  // uint32 per A buffer
#define B_U32 8192                  // uint32 per B buffer
#define OF_AS   0
#define OF_BS   (2 * A_U32)
#define OF_WQ   (OF_BS + 2 * B_U32)
#define OF_V    (OF_WQ + D_)
#define OF_PART (OF_V + D_)
#define SMEM_U32 (OF_PART + TM * 8)
#define SMEM_BYTES (SMEM_U32 * 4)

__global__ void __launch_bounds__(512, 1)
scores_kernel(const float* __restrict__ mb, const float* __restrict__ vvec,
              const void* __restrict__ lens) {
    const int b  = blockIdx.y;
    const int s0 = blockIdx.x * TM;
    // masked rows are never consumed downstream: skip dead tiles
    if (s0 >= load_len(lens, b)) return;

    extern __shared__ __align__(16) uint32_t sm[];
    uint32_t* As = sm + OF_AS;
    float* swq   = (float*)(sm + OF_WQ);
    float* sv    = (float*)(sm + OF_V);
    float* spart = (float*)(sm + OF_PART);

    const int tid = threadIdx.x;
    const int wid = tid >> 5, lane = tid & 31;
    const int g = lane >> 2, t = lane & 3;
    const int wr = wid >> 3, wc = wid & 7;
    const int m0 = wr * 32, n0 = wc * 64;

    for (int i = tid; i < D_; i += 512) {
        swq[i] = g_wq[b * D_ + i];
        sv[i]  = vvec[i];
    }

    // A staging: thread -> (row = tid>>3, 4 k at koff=(tid&7)*4)
    const int am   = tid >> 3;
    const int koff = (tid & 7) * 4;
    const float* a_gbase = mb + (size_t)b * S_ * D_ + (size_t)(s0 + am) * D_ + koff;
    const uint32_t sbase = smem_u32(sm);
    int i0;
    {
        int kk = koff >> 4;
        int tt = (koff & 7) >> 1;
        int kq = (koff & 15) >> 3;
        int gg = am & 7, pm = (am >> 3) & 1, awr = (am >> 5) & 1, mt = (am >> 4) & 1;
        i0 = ((kk * 2 + awr) * 2 + mt) * 128 + (gg * 4 + tt) * 4 + (kq * 2 + pm);
    }

    float acc[2][8][4];
#pragma unroll
    for (int mt = 0; mt < 2; ++mt)
#pragma unroll
        for (int j = 0; j < 8; ++j)
#pragma unroll
            for (int q = 0; q < 4; ++q) acc[mt][j][q] = 0.f;

#define STAGE_B(kb_, buf_) do {                                            \
        const uint4* bsrc4 = g_wcH + (kb_) * 2048;                         \
        uint32_t bdst = sbase + (OF_BS + (buf_) * B_U32) * 4;              \
        _Pragma("unroll")                                                  \
        for (int c = 0; c < 4; ++c) {                                      \
            int fi = tid + c * 512;                                        \
            cp_async16(bdst + fi * 16, bsrc4 + fi);                        \
        }                                                                  \
    } while (0)

    // ---- prologue: stage tile 0 ----
    {
        STAGE_B(0, 0);
        asm volatile("cp.async.commit_group;" ::: "memory");
        float4 av = *(const float4*)a_gbase;
        As[i0]     = packh2(av.x, av.y);
        As[i0 + 4] = packh2(av.z, av.w);
    }

#pragma unroll 1
    for (int kb = 0; kb < NKT; ++kb) {
        const int cur = kb & 1;
        float4 av;
        if (kb < NKT - 1) {
            av = *(const float4*)(a_gbase + (kb + 1) * TK);
            STAGE_B(kb + 1, cur ^ 1);
            asm volatile("cp.async.commit_group;" ::: "memory");
            asm volatile("cp.async.wait_group 1;" ::: "memory");
        } else {
            asm volatile("cp.async.wait_group 0;" ::: "memory");
        }
        __syncthreads();

        const uint32_t* Ac = As + cur * A_U32;
        const uint4* Bc = (const uint4*)(sm + OF_BS + cur * B_U32);
#pragma unroll
        for (int kk = 0; kk < 2; ++kk) {
            uint32_t a[2][4];
#pragma unroll
            for (int mt = 0; mt < 2; ++mt) {
                uint4 af = *(const uint4*)(Ac + ((kk * 2 + wr) * 2 + mt) * 128 + lane * 4);
                a[mt][0] = af.x; a[mt][1] = af.y; a[mt][2] = af.z; a[mt][3] = af.w;
            }
            const uint4* brow = Bc + ((kk * 8 + wc) * 4) * 32 + lane;
#pragma unroll
            for (int j2 = 0; j2 < 4; ++j2) {
                uint4 bf = brow[j2 * 32];
                mma_fp16(acc[0][j2 * 2],     a[0], bf.x, bf.y);
                mma_fp16(acc[1][j2 * 2],     a[1], bf.x, bf.y);
                mma_fp16(acc[0][j2 * 2 + 1], a[0], bf.z, bf.w);
                mma_fp16(acc[1][j2 * 2 + 1], a[1], bf.z, bf.w);
            }
        }

        if (kb < NKT - 1) {
            uint32_t* Ad = As + (cur ^ 1) * A_U32;
            Ad[i0]     = packh2(av.x, av.y);
            Ad[i0 + 4] = packh2(av.z, av.w);
        }
        __syncthreads();
    }

    // ---- epilogue: tanh + v dot, reduce ----
    float p[4] = {0.f, 0.f, 0.f, 0.f};
#pragma unroll
    for (int mt = 0; mt < 2; ++mt)
#pragma unroll
        for (int j = 0; j < 8; ++j) {
            const int c = n0 + j * 8 + 2 * t;
            const float v0 = sv[c], v1 = sv[c + 1];
            const float w0 = swq[c], w1 = swq[c + 1];
            p[mt * 2 + 0] += fast_tanh(w0 + acc[mt][j][0]) * v0 +
                             fast_tanh(w1 + acc[mt][j][1]) * v1;
            p[mt * 2 + 1] += fast_tanh(w0 + acc[mt][j][2]) * v0 +
                             fast_tanh(w1 + acc[mt][j][3]) * v1;
        }
#pragma unroll
    for (int q = 0; q < 4; ++q) {
        p[q] += __shfl_xor_sync(0xFFFFFFFFu, p[q], 1);
        p[q] += __shfl_xor_sync(0xFFFFFFFFu, p[q], 2);
    }
    if (t == 0) {
#pragma unroll
        for (int mt = 0; mt < 2; ++mt) {
            spart[(m0 + mt * 16 + g) * 8 + wc]     = p[mt * 2 + 0];
            spart[(m0 + mt * 16 + g + 8) * 8 + wc] = p[mt * 2 + 1];
        }
    }
    __syncthreads();
    if (tid < TM) {
        float s = 0.f;
#pragma unroll
        for (int w = 0; w < 8; ++w) s += spart[tid * 8 + w];
        g_scores[b * S_ + s0 + tid] = s;
    }
}

// ============================================================
// Kernel 3: masked softmax stats (loops clamped to len). grid B, block 1024
// ============================================================
__global__ void stats_kernel(const void* __restrict__ lens) {
    __shared__ float red[1024];
    int b = blockIdx.x, tid = threadIdx.x;
    int len = load_len(lens, b);

    float m = -3.4e38f;
    for (int s = tid; s < len; s += 1024)
        m = fmaxf(m, g_scores[b * S_ + s]);
    red[tid] = m;
    __syncthreads();
    for (int o = 512; o > 0; o >>= 1) {
        if (tid < o) red[tid] = fmaxf(red[tid], red[tid + o]);
        __syncthreads();
    }
    m = red[0];
    __syncthreads();

    float sum = 0.f;
    for (int s = tid; s < len; s += 1024)
        sum += __expf(g_scores[b * S_ + s] - m);
    red[tid] = sum;
    __syncthreads();
    for (int o = 512; o > 0; o >>= 1) {
        if (tid < o) red[tid] += red[tid + o];
        __syncthreads();
    }
    if (tid == 0) { g_stats[2 * b] = m; g_stats[2 * b + 1] = red[0]; }
}

// ============================================================
// Kernel 4a: context partials (fp32 mb, float2/thread, length-clamped).
// grid (8, B): x = sch. block 256: thread owns d-pair d2 = 2*tid, all 512 cols.
// ============================================================
__global__ void __launch_bounds__(256)
context_part_kernel(const float* __restrict__ mb,
                    const void* __restrict__ lens,
                    float* __restrict__ out) {
    __shared__ float w[256];
    int b = blockIdx.y, tid = threadIdx.x;
    int sch = blockIdx.x;
    int len = load_len(lens, b);
    int sbase = sch * 256;
    int d2 = tid * 2;
    float* align_out = out + B_ * D_;

    if (sbase >= len) {   // dead chunk: zero align + partials, no reads
        align_out[b * S_ + sbase + tid] = 0.f;
        g_ctx[sch][b * D_ + d2]     = 0.f;
        g_ctx[sch][b * D_ + d2 + 1] = 0.f;
        return;
    }

    float m = g_stats[2 * b];
    float inv = __fdividef(1.f, g_stats[2 * b + 1]);
    int cnt = min(256, len - sbase);

    w[tid] = (tid < cnt) ? __expf(g_scores[b * S_ + sbase + tid] - m) * inv : 0.f;
    __syncthreads();
    align_out[b * S_ + sbase + tid] = w[tid];

    const float2* p = (const float2*)(mb + (size_t)b * S_ * D_ +
                                      (size_t)sbase * D_ + d2);
    float a0 = 0.f, a1 = 0.f;
    if (cnt == 256) {
#pragma unroll 8
        for (int i = 0; i < 256; ++i) {
            float2 h = p[(size_t)i * (D_ / 2)];
            a0 += w[i] * h.x;
            a1 += w[i] * h.y;
        }
    } else {
#pragma unroll 4
        for (int i = 0; i < cnt; ++i) {
            float2 h = p[(size_t)i * (D_ / 2)];
            a0 += w[i] * h.x;
            a1 += w[i] * h.y;
        }
    }
    g_ctx[sch][b * D_ + d2]     = a0;
    g_ctx[sch][b * D_ + d2 + 1] = a1;
}

// ============================================================
// Kernel 4b: combine context partials. grid B, block 128
// ============================================================
__global__ void combine_kernel(float* __restrict__ out) {
    int b = blockIdx.x, tid = threadIdx.x;
    for (int d = tid; d < D_; d += 128) {
        int i = b * D_ + d;
        float s = 0.f;
#pragma unroll
        for (int c = 0; c < NSCH; ++c) s += g_ctx[c][i];
        out[i] = s;
    }
}

// ============================================================
extern "C" void kernel_launch(void* const* d_in, const int* in_sizes, int n_in,
                              void* d_out, int out_size) {
    const float* source = (const float*)d_in[0];
    const float* mb     = (const float*)d_in[1];
    const void*  lens   = (const void*)d_in[2];
    const float* Wq     = (const float*)d_in[3];
    const float* bq     = (const float*)d_in[4];
    const float* Wc     = (const float*)d_in[5];
    const float* v      = (const float*)d_in[6];
    float*       out    = (float*)d_out;

    cudaFuncSetAttribute(scores_kernel,
                         cudaFuncAttributeMaxDynamicSharedMemorySize, SMEM_BYTES);

    prep_kernel<<<128, 512>>>(Wc, source, Wq, bq);
    scores_kernel<<<dim3(S_ / TM, B_), 512, SMEM_BYTES>>>(mb, v, lens);
    stats_kernel<<<B_, 1024>>>(lens);
    context_part_kernel<<<dim3(NSCH, B_), 256>>>(mb, lens, out);
    combine_kernel<<<B_, 128>>>(out);
}

// round 13
// speedup vs baseline: 1.8760x; 1.0184x over previous
#include <cuda_runtime.h>
#include <cuda_fp16.h>
#include <cstdint>

#define B_ 64
#define S_ 2048
#define D_ 512

#define TM 64            // M rows per CTA
#define TK 32            // K per stage tile
#define NKT (D_ / TK)    // 16 k-tiles
#define NSCH 8           // context S-chunks
#define NPART (NSCH * 2) // context partials (2 s-halves per chunk)

// ---------------- scratch globals ----------------
__device__ float g_wq[B_ * D_];
__device__ float g_scores[B_ * S_];
__device__ float g_stats[2 * B_];
__device__ float g_ctx[NPART][B_ * D_];
// Wc as fp16 in m16n8k16-fragment order
__device__ __align__(16) uint4 g_wcH[NKT * 2048];

// ---------------- helpers ----------------
__device__ __forceinline__ float fast_tanh(float x) {
    float xc = fminf(fmaxf(x, -15.f), 15.f);
    float e = __expf(2.f * xc);
    return __fdividef(e - 1.f, e + 1.f);
}
// memory_lengths dtype sniff (int64 vs int32): word[1]==0 iff int64 (LE)
__device__ __forceinline__ int load_len(const void* lens, int b) {
    const int* p32 = (const int*)lens;
    if (p32[1] == 0) return (int)((const long long*)lens)[b];
    return p32[b];
}
__device__ __forceinline__ uint32_t smem_u32(const void* p) {
    uint32_t a;
    asm("{ .reg .u64 t; cvta.to.shared.u64 t, %1; cvt.u32.u64 %0, t; }" : "=r"(a) : "l"(p));
    return a;
}
__device__ __forceinline__ void cp_async16(uint32_t dst, const void* src) {
    asm volatile("cp.async.cg.shared.global [%0], [%1], 16;" :: "r"(dst), "l"(src));
}
__device__ __forceinline__ uint32_t packh2(float a, float b) {
    __half2 h = __floats2half2_rn(a, b);
    return *(uint32_t*)&h;
}
__device__ __forceinline__ void mma_fp16(float* c, const uint32_t* a,
                                         uint32_t b0, uint32_t b1) {
    asm volatile(
        "mma.sync.aligned.m16n8k16.row.col.f32.f16.f16.f32 "
        "{%0,%1,%2,%3}, {%4,%5,%6,%7}, {%8,%9}, {%0,%1,%2,%3};"
        : "+f"(c[0]), "+f"(c[1]), "+f"(c[2]), "+f"(c[3])
        : "r"(a[0]), "r"(a[1]), "r"(a[2]), "r"(a[3]), "r"(b0), "r"(b1));
}

// ============================================================
// Kernel 0: fused prep (Wc -> fp16 fragment order) + wq GEMV.
// grid 128, block 512. bid<64: prep; bid>=64: wq for batch bid-64.
// ============================================================
__global__ void prep_kernel(const float* __restrict__ Wc,
                            const float* __restrict__ src,
                            const float* __restrict__ Wq,
                            const float* __restrict__ bq) {
    int bid = blockIdx.x, tid = threadIdx.x;
    if (bid < 64) {
        int p = bid * 512 + tid;     // 32768 uint4
        int lane = p & 31;
        int j2   = (p >> 5) & 3;
        int wc   = (p >> 7) & 7;
        int kk   = (p >> 10) & 1;
        int kb   = (p >> 11) & 15;
        int g = lane >> 2, t = lane & 3;
        int ne = wc * 64 + j2 * 16 + g;
        int no = ne + 8;
        int k0 = kb * 32 + kk * 16 + 2 * t;
        const float* we = Wc + (size_t)ne * D_;
        const float* wo = Wc + (size_t)no * D_;
        uint4 f;
        f.x = packh2(we[k0],     we[k0 + 1]);
        f.y = packh2(we[k0 + 8], we[k0 + 9]);
        f.z = packh2(wo[k0],     wo[k0 + 1]);
        f.w = packh2(wo[k0 + 8], wo[k0 + 9]);
        g_wcH[p] = f;
    } else {
        int b = bid - 64;
        int e = tid;
        __shared__ __align__(16) float s_src[D_];
        s_src[tid] = src[b * D_ + tid];
        __syncthreads();
        const float4* w4 = (const float4*)(Wq + (size_t)e * D_);
        const float4* s4 = (const float4*)s_src;
        float acc = 0.f;
#pragma unroll 8
        for (int i = 0; i < D_ / 4; ++i) {
            float4 wv = w4[i], xv = s4[i];
            acc += wv.x * xv.x + wv.y * xv.y + wv.z * xv.z + wv.w * xv.w;
        }
        g_wq[b * D_ + e] = acc + bq[e];
    }
}

// ============================================================
// Kernel 2: fused scores, fp16 m16n8k16, double-buffered +
// early exit for s-tiles entirely beyond memory_lengths[b].
// grid (S/64, B), block 512 (2wr x 8wc). Warp tile m32 x n64.
// ============================================================
#define A_U32 1024                  // uint32 per A buffer
#define B_U32 8192                  // uint32 per B buffer
#define OF_AS   0
#define OF_BS   (2 * A_U32)
#define OF_WQ   (OF_BS + 2 * B_U32)
#define OF_V    (OF_WQ + D_)
#define OF_PART (OF_V + D_)
#define SMEM_U32 (OF_PART + TM * 8)
#define SMEM_BYTES (SMEM_U32 * 4)

__global__ void __launch_bounds__(512, 1)
scores_kernel(const float* __restrict__ mb, const float* __restrict__ vvec,
              const void* __restrict__ lens) {
    const int b  = blockIdx.y;
    const int s0 = blockIdx.x * TM;
    // masked rows are never consumed downstream: skip dead tiles
    if (s0 >= load_len(lens, b)) return;

    extern __shared__ __align__(16) uint32_t sm[];
    uint32_t* As = sm + OF_AS;
    float* swq   = (float*)(sm + OF_WQ);
    float* sv    = (float*)(sm + OF_V);
    float* spart = (float*)(sm + OF_PART);

    const int tid = threadIdx.x;
    const int wid = tid >> 5, lane = tid & 31;
    const int g = lane >> 2, t = lane & 3;
    const int wr = wid >> 3, wc = wid & 7;
    const int m0 = wr * 32, n0 = wc * 64;

    for (int i = tid; i < D_; i += 512) {
        swq[i] = g_wq[b * D_ + i];
        sv[i]  = vvec[i];
    }

    // A staging: thread -> (row = tid>>3, 4 k at koff=(tid&7)*4)
    const int am   = tid >> 3;
    const int koff = (tid & 7) * 4;
    const float* a_gbase = mb + (size_t)b * S_ * D_ + (size_t)(s0 + am) * D_ + koff;
    const uint32_t sbase = smem_u32(sm);
    int i0;
    {
        int kk = koff >> 4;
        int tt = (koff & 7) >> 1;
        int kq = (koff & 15) >> 3;
        int gg = am & 7, pm = (am >> 3) & 1, awr = (am >> 5) & 1, mt = (am >> 4) & 1;
        i0 = ((kk * 2 + awr) * 2 + mt) * 128 + (gg * 4 + tt) * 4 + (kq * 2 + pm);
    }

    float acc[2][8][4];
#pragma unroll
    for (int mt = 0; mt < 2; ++mt)
#pragma unroll
        for (int j = 0; j < 8; ++j)
#pragma unroll
            for (int q = 0; q < 4; ++q) acc[mt][j][q] = 0.f;

#define STAGE_B(kb_, buf_) do {                                            \
        const uint4* bsrc4 = g_wcH + (kb_) * 2048;                         \
        uint32_t bdst = sbase + (OF_BS + (buf_) * B_U32) * 4;              \
        _Pragma("unroll")                                                  \
        for (int c = 0; c < 4; ++c) {                                      \
            int fi = tid + c * 512;                                        \
            cp_async16(bdst + fi * 16, bsrc4 + fi);                        \
        }                                                                  \
    } while (0)

    // ---- prologue: stage tile 0 ----
    {
        STAGE_B(0, 0);
        asm volatile("cp.async.commit_group;" ::: "memory");
        float4 av = *(const float4*)a_gbase;
        As[i0]     = packh2(av.x, av.y);
        As[i0 + 4] = packh2(av.z, av.w);
    }

#pragma unroll 1
    for (int kb = 0; kb < NKT; ++kb) {
        const int cur = kb & 1;
        float4 av;
        if (kb < NKT - 1) {
            av = *(const float4*)(a_gbase + (kb + 1) * TK);
            STAGE_B(kb + 1, cur ^ 1);
            asm volatile("cp.async.commit_group;" ::: "memory");
            asm volatile("cp.async.wait_group 1;" ::: "memory");
        } else {
            asm volatile("cp.async.wait_group 0;" ::: "memory");
        }
        __syncthreads();

        const uint32_t* Ac = As + cur * A_U32;
        const uint4* Bc = (const uint4*)(sm + OF_BS + cur * B_U32);
#pragma unroll
        for (int kk = 0; kk < 2; ++kk) {
            uint32_t a[2][4];
#pragma unroll
            for (int mt = 0; mt < 2; ++mt) {
                uint4 af = *(const uint4*)(Ac + ((kk * 2 + wr) * 2 + mt) * 128 + lane * 4);
                a[mt][0] = af.x; a[mt][1] = af.y; a[mt][2] = af.z; a[mt][3] = af.w;
            }
            const uint4* brow = Bc + ((kk * 8 + wc) * 4) * 32 + lane;
#pragma unroll
            for (int j2 = 0; j2 < 4; ++j2) {
                uint4 bf = brow[j2 * 32];
                mma_fp16(acc[0][j2 * 2],     a[0], bf.x, bf.y);
                mma_fp16(acc[1][j2 * 2],     a[1], bf.x, bf.y);
                mma_fp16(acc[0][j2 * 2 + 1], a[0], bf.z, bf.w);
                mma_fp16(acc[1][j2 * 2 + 1], a[1], bf.z, bf.w);
            }
        }

        if (kb < NKT - 1) {
            uint32_t* Ad = As + (cur ^ 1) * A_U32;
            Ad[i0]     = packh2(av.x, av.y);
            Ad[i0 + 4] = packh2(av.z, av.w);
        }
        __syncthreads();
    }

    // ---- epilogue: tanh + v dot, reduce ----
    float p[4] = {0.f, 0.f, 0.f, 0.f};
#pragma unroll
    for (int mt = 0; mt < 2; ++mt)
#pragma unroll
        for (int j = 0; j < 8; ++j) {
            const int c = n0 + j * 8 + 2 * t;
            const float v0 = sv[c], v1 = sv[c + 1];
            const float w0 = swq[c], w1 = swq[c + 1];
            p[mt * 2 + 0] += fast_tanh(w0 + acc[mt][j][0]) * v0 +
                             fast_tanh(w1 + acc[mt][j][1]) * v1;
            p[mt * 2 + 1] += fast_tanh(w0 + acc[mt][j][2]) * v0 +
                             fast_tanh(w1 + acc[mt][j][3]) * v1;
        }
#pragma unroll
    for (int q = 0; q < 4; ++q) {
        p[q] += __shfl_xor_sync(0xFFFFFFFFu, p[q], 1);
        p[q] += __shfl_xor_sync(0xFFFFFFFFu, p[q], 2);
    }
    if (t == 0) {
#pragma unroll
        for (int mt = 0; mt < 2; ++mt) {
            spart[(m0 + mt * 16 + g) * 8 + wc]     = p[mt * 2 + 0];
            spart[(m0 + mt * 16 + g + 8) * 8 + wc] = p[mt * 2 + 1];
        }
    }
    __syncthreads();
    if (tid < TM) {
        float s = 0.f;
#pragma unroll
        for (int w = 0; w < 8; ++w) s += spart[tid * 8 + w];
        g_scores[b * S_ + s0 + tid] = s;
    }
}

// ============================================================
// Kernel 3: masked softmax stats (loops clamped to len). grid B, block 1024
// ============================================================
__global__ void stats_kernel(const void* __restrict__ lens) {
    __shared__ float red[1024];
    int b = blockIdx.x, tid = threadIdx.x;
    int len = load_len(lens, b);

    float m = -3.4e38f;
    for (int s = tid; s < len; s += 1024)
        m = fmaxf(m, g_scores[b * S_ + s]);
    red[tid] = m;
    __syncthreads();
    for (int o = 512; o > 0; o >>= 1) {
        if (tid < o) red[tid] = fmaxf(red[tid], red[tid + o]);
        __syncthreads();
    }
    m = red[0];
    __syncthreads();

    float sum = 0.f;
    for (int s = tid; s < len; s += 1024)
        sum += __expf(g_scores[b * S_ + s] - m);
    red[tid] = sum;
    __syncthreads();
    for (int o = 512; o > 0; o >>= 1) {
        if (tid < o) red[tid] += red[tid + o];
        __syncthreads();
    }
    if (tid == 0) { g_stats[2 * b] = m; g_stats[2 * b + 1] = red[0]; }
}

// ============================================================
// Kernel 4a: context partials. grid (NSCH, B), block 256.
// Thread layout: dd = (tid&127)*4 (float4 over D), sh = tid>>7 (s-half of 128).
// Each thread: <=128 iters of float4 loads -> high bytes-in-flight.
// ============================================================
__global__ void __launch_bounds__(256)
context_part_kernel(const float* __restrict__ mb,
                    const void* __restrict__ lens,
                    float* __restrict__ out) {
    __shared__ float w[256];
    int b = blockIdx.y, tid = threadIdx.x;
    int sch = blockIdx.x;
    int len = load_len(lens, b);
    int sbase = sch * 256;
    int dd = (tid & 127) * 4;
    int sh = tid >> 7;
    int part = sch * 2 + sh;
    float* align_out = out + B_ * D_;
    float* ctx = g_ctx[part] + b * D_ + dd;

    if (sbase >= len) {   // dead chunk: zero align + partials, no reads
        align_out[b * S_ + sbase + tid] = 0.f;
        *(float4*)ctx = make_float4(0.f, 0.f, 0.f, 0.f);
        return;
    }

    float m = g_stats[2 * b];
    float inv = __fdividef(1.f, g_stats[2 * b + 1]);
    int cnt = min(256, len - sbase);

    w[tid] = (tid < cnt) ? __expf(g_scores[b * S_ + sbase + tid] - m) * inv : 0.f;
    __syncthreads();
    align_out[b * S_ + sbase + tid] = w[tid];

    int si0 = sh * 128;
    int scnt = min(128, max(0, cnt - si0));   // rows this half processes
    const float4* p = (const float4*)(mb + (size_t)b * S_ * D_ +
                                      (size_t)(sbase + si0) * D_ + dd);
    float4 a = make_float4(0.f, 0.f, 0.f, 0.f);
    const float* wh = w + si0;
    if (scnt == 128) {
#pragma unroll 8
        for (int i = 0; i < 128; ++i) {
            float4 h = p[(size_t)i * (D_ / 4)];
            float ww = wh[i];
            a.x += ww * h.x; a.y += ww * h.y;
            a.z += ww * h.z; a.w += ww * h.w;
        }
    } else {
#pragma unroll 4
        for (int i = 0; i < scnt; ++i) {
            float4 h = p[(size_t)i * (D_ / 4)];
            float ww = wh[i];
            a.x += ww * h.x; a.y += ww * h.y;
            a.z += ww * h.z; a.w += ww * h.w;
        }
    }
    *(float4*)ctx = a;
}

// ============================================================
// Kernel 4b: combine context partials. grid B, block 128
// ============================================================
__global__ void combine_kernel(float* __restrict__ out) {
    int b = blockIdx.x, tid = threadIdx.x;
    for (int d = tid; d < D_; d += 128) {
        int i = b * D_ + d;
        float s = 0.f;
#pragma unroll
        for (int c = 0; c < NPART; ++c) s += g_ctx[c][i];
        out[i] = s;
    }
}

// ============================================================
extern "C" void kernel_launch(void* const* d_in, const int* in_sizes, int n_in,
                              void* d_out, int out_size) {
    const float* source = (const float*)d_in[0];
    const float* mb     = (const float*)d_in[1];
    const void*  lens   = (const void*)d_in[2];
    const float* Wq     = (const float*)d_in[3];
    const float* bq     = (const float*)d_in[4];
    const float* Wc     = (const float*)d_in[5];
    const float* v      = (const float*)d_in[6];
    float*       out    = (float*)d_out;

    cudaFuncSetAttribute(scores_kernel,
                         cudaFuncAttributeMaxDynamicSharedMemorySize, SMEM_BYTES);

    prep_kernel<<<128, 512>>>(Wc, source, Wq, bq);
    scores_kernel<<<dim3(S_ / TM, B_), 512, SMEM_BYTES>>>(mb, v, lens);
    stats_kernel<<<B_, 1024>>>(lens);
    context_part_kernel<<<dim3(NSCH, B_), 256>>>(mb, lens, out);
    combine_kernel<<<B_, 128>>>(out);
}

// round 14
// speedup vs baseline: 1.9601x; 1.0449x over previous
#include <cuda_runtime.h>
#include <cuda_fp16.h>
#include <cstdint>

#define B_ 64
#define S_ 2048
#define D_ 512

#define TM 64            // M rows per CTA
#define TK 32            // K per stage tile
#define NKT (D_ / TK)    // 16 k-tiles
#define CCH 64           // context rows per chunk
#define NCCH (S_ / CCH)  // 32 context chunks
#define NPART NCCH       // context partials per batch

// ---------------- scratch globals ----------------
__device__ float g_wq[B_ * D_];
__device__ float g_scores[B_ * S_];
__device__ float g_stats[2 * B_];
__device__ float g_ctx[NPART][B_ * D_];
// Wc as fp16 in m16n8k16-fragment order
__device__ __align__(16) uint4 g_wcH[NKT * 2048];

// ---------------- helpers ----------------
__device__ __forceinline__ float fast_tanh(float x) {
    float xc = fminf(fmaxf(x, -15.f), 15.f);
    float e = __expf(2.f * xc);
    return __fdividef(e - 1.f, e + 1.f);
}
// memory_lengths dtype sniff (int64 vs int32): word[1]==0 iff int64 (LE)
__device__ __forceinline__ int load_len(const void* lens, int b) {
    const int* p32 = (const int*)lens;
    if (p32[1] == 0) return (int)((const long long*)lens)[b];
    return p32[b];
}
__device__ __forceinline__ uint32_t smem_u32(const void* p) {
    uint32_t a;
    asm("{ .reg .u64 t; cvta.to.shared.u64 t, %1; cvt.u32.u64 %0, t; }" : "=r"(a) : "l"(p));
    return a;
}
__device__ __forceinline__ void cp_async16(uint32_t dst, const void* src) {
    asm volatile("cp.async.cg.shared.global [%0], [%1], 16;" :: "r"(dst), "l"(src));
}
__device__ __forceinline__ uint32_t packh2(float a, float b) {
    __half2 h = __floats2half2_rn(a, b);
    return *(uint32_t*)&h;
}
__device__ __forceinline__ void mma_fp16(float* c, const uint32_t* a,
                                         uint32_t b0, uint32_t b1) {
    asm volatile(
        "mma.sync.aligned.m16n8k16.row.col.f32.f16.f16.f32 "
        "{%0,%1,%2,%3}, {%4,%5,%6,%7}, {%8,%9}, {%0,%1,%2,%3};"
        : "+f"(c[0]), "+f"(c[1]), "+f"(c[2]), "+f"(c[3])
        : "r"(a[0]), "r"(a[1]), "r"(a[2]), "r"(a[3]), "r"(b0), "r"(b1));
}

// ============================================================
// Kernel 0: fused prep (Wc -> fp16 fragment order) + wq GEMV.
// grid 128, block 512. bid<64: prep; bid>=64: wq for batch bid-64.
// ============================================================
__global__ void prep_kernel(const float* __restrict__ Wc,
                            const float* __restrict__ src,
                            const float* __restrict__ Wq,
                            const float* __restrict__ bq) {
    int bid = blockIdx.x, tid = threadIdx.x;
    if (bid < 64) {
        int p = bid * 512 + tid;     // 32768 uint4
        int lane = p & 31;
        int j2   = (p >> 5) & 3;
        int wc   = (p >> 7) & 7;
        int kk   = (p >> 10) & 1;
        int kb   = (p >> 11) & 15;
        int g = lane >> 2, t = lane & 3;
        int ne = wc * 64 + j2 * 16 + g;
        int no = ne + 8;
        int k0 = kb * 32 + kk * 16 + 2 * t;
        const float* we = Wc + (size_t)ne * D_;
        const float* wo = Wc + (size_t)no * D_;
        uint4 f;
        f.x = packh2(we[k0],     we[k0 + 1]);
        f.y = packh2(we[k0 + 8], we[k0 + 9]);
        f.z = packh2(wo[k0],     wo[k0 + 1]);
        f.w = packh2(wo[k0 + 8], wo[k0 + 9]);
        g_wcH[p] = f;
    } else {
        int b = bid - 64;
        int e = tid;
        __shared__ __align__(16) float s_src[D_];
        s_src[tid] = src[b * D_ + tid];
        __syncthreads();
        const float4* w4 = (const float4*)(Wq + (size_t)e * D_);
        const float4* s4 = (const float4*)s_src;
        float acc = 0.f;
#pragma unroll 8
        for (int i = 0; i < D_ / 4; ++i) {
            float4 wv = w4[i], xv = s4[i];
            acc += wv.x * xv.x + wv.y * xv.y + wv.z * xv.z + wv.w * xv.w;
        }
        g_wq[b * D_ + e] = acc + bq[e];
    }
}

// ============================================================
// Kernel 2: fused scores, fp16 m16n8k16, double-buffered +
// early exit for s-tiles entirely beyond memory_lengths[b].
// grid (S/64, B), block 512 (2wr x 8wc). Warp tile m32 x n64.
// ============================================================
#define A_U32 1024                  // uint32 per A buffer
#define B_U32 8192                  // uint32 per B buffer
#define OF_AS   0
#define OF_BS   (2 * A_U32)
#define OF_WQ   (OF_BS + 2 * B_U32)
#define OF_V    (OF_WQ + D_)
#define OF_PART (OF_V + D_)
#define SMEM_U32 (OF_PART + TM * 8)
#define SMEM_BYTES (SMEM_U32 * 4)

__global__ void __launch_bounds__(512, 1)
scores_kernel(const float* __restrict__ mb, const float* __restrict__ vvec,
              const void* __restrict__ lens) {
    const int b  = blockIdx.y;
    const int s0 = blockIdx.x * TM;
    // masked rows are never consumed downstream: skip dead tiles
    if (s0 >= load_len(lens, b)) return;

    extern __shared__ __align__(16) uint32_t sm[];
    uint32_t* As = sm + OF_AS;
    float* swq   = (float*)(sm + OF_WQ);
    float* sv    = (float*)(sm + OF_V);
    float* spart = (float*)(sm + OF_PART);

    const int tid = threadIdx.x;
    const int wid = tid >> 5, lane = tid & 31;
    const int g = lane >> 2, t = lane & 3;
    const int wr = wid >> 3, wc = wid & 7;
    const int m0 = wr * 32, n0 = wc * 64;

    for (int i = tid; i < D_; i += 512) {
        swq[i] = g_wq[b * D_ + i];
        sv[i]  = vvec[i];
    }

    // A staging: thread -> (row = tid>>3, 4 k at koff=(tid&7)*4)
    const int am   = tid >> 3;
    const int koff = (tid & 7) * 4;
    const float* a_gbase = mb + (size_t)b * S_ * D_ + (size_t)(s0 + am) * D_ + koff;
    const uint32_t sbase = smem_u32(sm);
    int i0;
    {
        int kk = koff >> 4;
        int tt = (koff & 7) >> 1;
        int kq = (koff & 15) >> 3;
        int gg = am & 7, pm = (am >> 3) & 1, awr = (am >> 5) & 1, mt = (am >> 4) & 1;
        i0 = ((kk * 2 + awr) * 2 + mt) * 128 + (gg * 4 + tt) * 4 + (kq * 2 + pm);
    }

    float acc[2][8][4];
#pragma unroll
    for (int mt = 0; mt < 2; ++mt)
#pragma unroll
        for (int j = 0; j < 8; ++j)
#pragma unroll
            for (int q = 0; q < 4; ++q) acc[mt][j][q] = 0.f;

#define STAGE_B(kb_, buf_) do {                                            \
        const uint4* bsrc4 = g_wcH + (kb_) * 2048;                         \
        uint32_t bdst = sbase + (OF_BS + (buf_) * B_U32) * 4;              \
        _Pragma("unroll")                                                  \
        for (int c = 0; c < 4; ++c) {                                      \
            int fi = tid + c * 512;                                        \
            cp_async16(bdst + fi * 16, bsrc4 + fi);                        \
        }                                                                  \
    } while (0)

    // ---- prologue: stage tile 0 ----
    {
        STAGE_B(0, 0);
        asm volatile("cp.async.commit_group;" ::: "memory");
        float4 av = *(const float4*)a_gbase;
        As[i0]     = packh2(av.x, av.y);
        As[i0 + 4] = packh2(av.z, av.w);
    }

#pragma unroll 1
    for (int kb = 0; kb < NKT; ++kb) {
        const int cur = kb & 1;
        float4 av;
        if (kb < NKT - 1) {
            av = *(const float4*)(a_gbase + (kb + 1) * TK);
            STAGE_B(kb + 1, cur ^ 1);
            asm volatile("cp.async.commit_group;" ::: "memory");
            asm volatile("cp.async.wait_group 1;" ::: "memory");
        } else {
            asm volatile("cp.async.wait_group 0;" ::: "memory");
        }
        __syncthreads();

        const uint32_t* Ac = As + cur * A_U32;
        const uint4* Bc = (const uint4*)(sm + OF_BS + cur * B_U32);
#pragma unroll
        for (int kk = 0; kk < 2; ++kk) {
            uint32_t a[2][4];
#pragma unroll
            for (int mt = 0; mt < 2; ++mt) {
                uint4 af = *(const uint4*)(Ac + ((kk * 2 + wr) * 2 + mt) * 128 + lane * 4);
                a[mt][0] = af.x; a[mt][1] = af.y; a[mt][2] = af.z; a[mt][3] = af.w;
            }
            const uint4* brow = Bc + ((kk * 8 + wc) * 4) * 32 + lane;
#pragma unroll
            for (int j2 = 0; j2 < 4; ++j2) {
                uint4 bf = brow[j2 * 32];
                mma_fp16(acc[0][j2 * 2],     a[0], bf.x, bf.y);
                mma_fp16(acc[1][j2 * 2],     a[1], bf.x, bf.y);
                mma_fp16(acc[0][j2 * 2 + 1], a[0], bf.z, bf.w);
                mma_fp16(acc[1][j2 * 2 + 1], a[1], bf.z, bf.w);
            }
        }

        if (kb < NKT - 1) {
            uint32_t* Ad = As + (cur ^ 1) * A_U32;
            Ad[i0]     = packh2(av.x, av.y);
            Ad[i0 + 4] = packh2(av.z, av.w);
        }
        __syncthreads();
    }

    // ---- epilogue: tanh + v dot, reduce ----
    float p[4] = {0.f, 0.f, 0.f, 0.f};
#pragma unroll
    for (int mt = 0; mt < 2; ++mt)
#pragma unroll
        for (int j = 0; j < 8; ++j) {
            const int c = n0 + j * 8 + 2 * t;
            const float v0 = sv[c], v1 = sv[c + 1];
            const float w0 = swq[c], w1 = swq[c + 1];
            p[mt * 2 + 0] += fast_tanh(w0 + acc[mt][j][0]) * v0 +
                             fast_tanh(w1 + acc[mt][j][1]) * v1;
            p[mt * 2 + 1] += fast_tanh(w0 + acc[mt][j][2]) * v0 +
                             fast_tanh(w1 + acc[mt][j][3]) * v1;
        }
#pragma unroll
    for (int q = 0; q < 4; ++q) {
        p[q] += __shfl_xor_sync(0xFFFFFFFFu, p[q], 1);
        p[q] += __shfl_xor_sync(0xFFFFFFFFu, p[q], 2);
    }
    if (t == 0) {
#pragma unroll
        for (int mt = 0; mt < 2; ++mt) {
            spart[(m0 + mt * 16 + g) * 8 + wc]     = p[mt * 2 + 0];
            spart[(m0 + mt * 16 + g + 8) * 8 + wc] = p[mt * 2 + 1];
        }
    }
    __syncthreads();
    if (tid < TM) {
        float s = 0.f;
#pragma unroll
        for (int w = 0; w < 8; ++w) s += spart[tid * 8 + w];
        g_scores[b * S_ + s0 + tid] = s;
    }
}

// ============================================================
// Kernel 3: masked softmax stats (loops clamped to len). grid B, block 1024
// ============================================================
__global__ void stats_kernel(const void* __restrict__ lens) {
    __shared__ float red[1024];
    int b = blockIdx.x, tid = threadIdx.x;
    int len = load_len(lens, b);

    float m = -3.4e38f;
    for (int s = tid; s < len; s += 1024)
        m = fmaxf(m, g_scores[b * S_ + s]);
    red[tid] = m;
    __syncthreads();
    for (int o = 512; o > 0; o >>= 1) {
        if (tid < o) red[tid] = fmaxf(red[tid], red[tid + o]);
        __syncthreads();
    }
    m = red[0];
    __syncthreads();

    float sum = 0.f;
    for (int s = tid; s < len; s += 1024)
        sum += __expf(g_scores[b * S_ + s] - m);
    red[tid] = sum;
    __syncthreads();
    for (int o = 512; o > 0; o >>= 1) {
        if (tid < o) red[tid] += red[tid + o];
        __syncthreads();
    }
    if (tid == 0) { g_stats[2 * b] = m; g_stats[2 * b + 1] = red[0]; }
}

// ============================================================
// Kernel 4a: context partials, fine-grained: 64 s-rows per CTA.
// grid (NCCH, B) = (32, 64), block 128: thread owns d-float4, loops 64 rows.
// ~1090 live CTAs -> 3.7x resident warps vs 256-row chunks.
// ============================================================
__global__ void __launch_bounds__(128)
context_part_kernel(const float* __restrict__ mb,
                    const void* __restrict__ lens,
                    float* __restrict__ out) {
    __shared__ float w[CCH];
    int b = blockIdx.y, tid = threadIdx.x;
    int sch = blockIdx.x;
    int len = load_len(lens, b);
    int sbase = sch * CCH;
    int dd = tid * 4;
    float* align_out = out + B_ * D_;
    float* ctx = g_ctx[sch] + b * D_ + dd;

    if (sbase >= len) {   // dead chunk: zero align + partials, no reads
        if (tid < CCH) align_out[b * S_ + sbase + tid] = 0.f;
        *(float4*)ctx = make_float4(0.f, 0.f, 0.f, 0.f);
        return;
    }

    float m = g_stats[2 * b];
    float inv = __fdividef(1.f, g_stats[2 * b + 1]);
    int cnt = min(CCH, len - sbase);

    if (tid < CCH) {
        float ww = (tid < cnt) ? __expf(g_scores[b * S_ + sbase + tid] - m) * inv : 0.f;
        w[tid] = ww;
        align_out[b * S_ + sbase + tid] = ww;
    }
    __syncthreads();

    const float4* p = (const float4*)(mb + (size_t)b * S_ * D_ +
                                      (size_t)sbase * D_ + dd);
    float4 a = make_float4(0.f, 0.f, 0.f, 0.f);
    if (cnt == CCH) {
#pragma unroll 8
        for (int i = 0; i < CCH; ++i) {
            float4 h = p[(size_t)i * (D_ / 4)];
            float ww = w[i];
            a.x += ww * h.x; a.y += ww * h.y;
            a.z += ww * h.z; a.w += ww * h.w;
        }
    } else {
#pragma unroll 4
        for (int i = 0; i < cnt; ++i) {
            float4 h = p[(size_t)i * (D_ / 4)];
            float ww = w[i];
            a.x += ww * h.x; a.y += ww * h.y;
            a.z += ww * h.z; a.w += ww * h.w;
        }
    }
    *(float4*)ctx = a;
}

// ============================================================
// Kernel 4b: combine context partials. grid B, block 128
// ============================================================
__global__ void combine_kernel(float* __restrict__ out) {
    int b = blockIdx.x, tid = threadIdx.x;
    for (int d = tid; d < D_; d += 128) {
        int i = b * D_ + d;
        float s = 0.f;
#pragma unroll
        for (int c = 0; c < NPART; ++c) s += g_ctx[c][i];
        out[i] = s;
    }
}

// ============================================================
extern "C" void kernel_launch(void* const* d_in, const int* in_sizes, int n_in,
                              void* d_out, int out_size) {
    const float* source = (const float*)d_in[0];
    const float* mb     = (const float*)d_in[1];
    const void*  lens   = (const void*)d_in[2];
    const float* Wq     = (const float*)d_in[3];
    const float* bq     = (const float*)d_in[4];
    const float* Wc     = (const float*)d_in[5];
    const float* v      = (const float*)d_in[6];
    float*       out    = (float*)d_out;

    cudaFuncSetAttribute(scores_kernel,
                         cudaFuncAttributeMaxDynamicSharedMemorySize, SMEM_BYTES);

    prep_kernel<<<128, 512>>>(Wc, source, Wq, bq);
    scores_kernel<<<dim3(S_ / TM, B_), 512, SMEM_BYTES>>>(mb, v, lens);
    stats_kernel<<<B_, 1024>>>(lens);
    context_part_kernel<<<dim3(NCCH, B_), 128>>>(mb, lens, out);
    combine_kernel<<<B_, 128>>>(out);
}